// round 2
// baseline (speedup 1.0000x reference)
#include <cuda_runtime.h>

#define AN 76725
#define NC 80
#define CA (AN * NC)
#define NBINS 2048
#define WCAP 2048
#define TARGET 1024
#define MAXKEEP 200
#define IMGF 640.0f
#define NMS_BS 256

// Scratch (device globals: no allocation allowed)
__device__ float g_clsT[CA];       // transposed scores [C, A]
__device__ float g_boxes[AN * 4];  // decoded boxes
__device__ float g_area[AN];

// ---------------------------------------------------------------------------
// Decode + clip boxes, precompute areas
// ---------------------------------------------------------------------------
__global__ void decode_kernel(const float* __restrict__ anchors,
                              const float* __restrict__ reg) {
    int i = blockIdx.x * blockDim.x + threadIdx.x;
    if (i >= AN) return;
    float a0 = anchors[i * 4 + 0], a1 = anchors[i * 4 + 1];
    float a2 = anchors[i * 4 + 2], a3 = anchors[i * 4 + 3];
    float r0 = reg[i * 4 + 0], r1 = reg[i * 4 + 1];
    float r2 = reg[i * 4 + 2], r3 = reg[i * 4 + 3];
    float aw = a2 - a0, ah = a3 - a1;
    float ax = a0 + 0.5f * aw, ay = a1 + 0.5f * ah;
    float cx = ax + r0 * 0.1f * aw;
    float cy = ay + r1 * 0.1f * ah;
    float w = aw * expf(r2 * 0.2f);
    float h = ah * expf(r3 * 0.2f);
    float x1 = fminf(fmaxf(cx - 0.5f * w, 0.0f), IMGF);
    float y1 = fminf(fmaxf(cy - 0.5f * h, 0.0f), IMGF);
    float x2 = fminf(fmaxf(cx + 0.5f * w, 0.0f), IMGF);
    float y2 = fminf(fmaxf(cy + 0.5f * h, 0.0f), IMGF);
    g_boxes[i * 4 + 0] = x1;
    g_boxes[i * 4 + 1] = y1;
    g_boxes[i * 4 + 2] = x2;
    g_boxes[i * 4 + 3] = y2;
    g_area[i] = (x2 - x1) * (y2 - y1);
}

// ---------------------------------------------------------------------------
// Transpose classification [A, C] -> [C, A] for coalesced per-class scans
// ---------------------------------------------------------------------------
__global__ void transpose_kernel(const float* __restrict__ cls) {
    __shared__ float tile[32][33];
    int a0 = blockIdx.x * 32, c0 = blockIdx.y * 32;
    int c = c0 + threadIdx.x, a = a0 + threadIdx.y;
    if (a < AN && c < NC) tile[threadIdx.y][threadIdx.x] = cls[a * NC + c];
    __syncthreads();
    int c2 = c0 + threadIdx.y, a2 = a0 + threadIdx.x;
    if (a2 < AN && c2 < NC) g_clsT[c2 * AN + a2] = tile[threadIdx.x][threadIdx.y];
}

// ---------------------------------------------------------------------------
// Fill defaults: scores=0, labels=-1, boxes=0, keep=0 (float4 stores)
// ---------------------------------------------------------------------------
__global__ void fill_kernel(float4* __restrict__ out4, int n4) {
    const int ca4 = CA / 4;
    int stride = gridDim.x * blockDim.x;
    for (int i = blockIdx.x * blockDim.x + threadIdx.x; i < n4; i += stride) {
        float v = (i >= ca4 && i < 2 * ca4) ? -1.0f : 0.0f;
        out4[i] = make_float4(v, v, v, v);
    }
}

// ---------------------------------------------------------------------------
// Per-class NMS: one block per class.
// ---------------------------------------------------------------------------
__global__ __launch_bounds__(NMS_BS) void nms_kernel(float* __restrict__ out) {
    const int c = blockIdx.x;
    const int tid = threadIdx.x;
    const float* cls = g_clsT + c * AN;

    __shared__ int hist[NBINS];
    __shared__ unsigned long long skey[WCAP];
    __shared__ float kx1[MAXKEEP], ky1a[MAXKEEP], kx2[MAXKEEP], ky2a[MAXKEEP];
    __shared__ float kar[MAXKEEP], ksc[MAXKEEP];
    __shared__ int kid[MAXKEEP];
    __shared__ int kcount, wn, wlo_s;
    __shared__ float cbx1[NMS_BS], cby1[NMS_BS], cbx2[NMS_BS], cby2[NMS_BS];
    __shared__ float car[NMS_BS], csc[NMS_BS];
    __shared__ int cid[NMS_BS];
    __shared__ unsigned char sflag[NMS_BS];

    for (int i = tid; i < NBINS; i += NMS_BS) hist[i] = 0;
    if (tid == 0) kcount = 0;
    __syncthreads();

    const float BK = (float)NBINS / 0.9f;
    for (int i = tid; i < AN; i += NMS_BS) {
        float s = cls[i];
        if (s > 0.1f) {
            int b = (int)((s - 0.1f) * BK);
            b = min(max(b, 0), NBINS - 1);
            atomicAdd(&hist[b], 1);
        }
    }
    __syncthreads();

    int hi = NBINS;
    while (hi > 0) {
        if (kcount >= MAXKEEP) break;  // uniform (kcount sync'd)

        // thread 0 picks score window [wlo, hi): >= TARGET candidates, <= WCAP
        if (tid == 0) {
            int lo = hi, acc = 0;
            while (lo > 0) {
                int h = hist[lo - 1];
                if (acc > 0 && acc + h > WCAP) break;
                lo--;
                acc += h;
                if (acc >= TARGET) break;
            }
            wlo_s = lo;
            wn = 0;
        }
        __syncthreads();
        int wlo = wlo_s;

        // gather window candidates into shared as (scoreBits<<32 | ~idx)
        for (int i = tid; i < AN; i += NMS_BS) {
            float s = cls[i];
            if (s > 0.1f) {
                int b = (int)((s - 0.1f) * BK);
                b = min(max(b, 0), NBINS - 1);
                if (b >= wlo && b < hi) {
                    int p = atomicAdd(&wn, 1);
                    if (p < WCAP)
                        skey[p] = ((unsigned long long)__float_as_uint(s) << 32) |
                                  (unsigned long long)(0xFFFFFFFFu - (unsigned)i);
                }
            }
        }
        __syncthreads();
        int n = min(wn, WCAP);

        if (n > 0) {
            // pad to pow2, bitonic sort descending
            int m = 1;
            while (m < n) m <<= 1;
            for (int i = n + tid; i < m; i += NMS_BS) skey[i] = 0ULL;
            __syncthreads();
            for (int k = 2; k <= m; k <<= 1) {
                for (int j = k >> 1; j > 0; j >>= 1) {
                    for (int i = tid; i < m; i += NMS_BS) {
                        int ixj = i ^ j;
                        if (ixj > i) {
                            bool desc = ((i & k) == 0);
                            unsigned long long a = skey[i], b = skey[ixj];
                            if (desc ? (a < b) : (a > b)) {
                                skey[i] = b;
                                skey[ixj] = a;
                            }
                        }
                    }
                    __syncthreads();
                }
            }

            // batched speculative greedy walk
            for (int base = 0; base < n; base += NMS_BS) {
                int kc = kcount;  // sync'd snapshot, uniform
                if (kc >= MAXKEEP) break;
                int p = base + tid;
                bool surv = false;
                if (p < n) {
                    unsigned long long key = skey[p];
                    float s = __uint_as_float((unsigned)(key >> 32));
                    int idx = (int)(0xFFFFFFFFu - (unsigned)key);
                    float bx1 = g_boxes[idx * 4 + 0], by1 = g_boxes[idx * 4 + 1];
                    float bx2 = g_boxes[idx * 4 + 2], by2 = g_boxes[idx * 4 + 3];
                    float ba = g_area[idx];
                    surv = true;
                    for (int j = 0; j < kc; j++) {
                        float ix1 = fmaxf(kx1[j], bx1), iy1 = fmaxf(ky1a[j], by1);
                        float ix2 = fminf(kx2[j], bx2), iy2 = fminf(ky2a[j], by2);
                        float inter = fmaxf(ix2 - ix1, 0.0f) * fmaxf(iy2 - iy1, 0.0f);
                        float iou = inter / ((kar[j] + ba) - inter);
                        if (iou > 0.5f) {
                            surv = false;
                            break;
                        }
                    }
                    if (surv) {
                        cbx1[tid] = bx1; cby1[tid] = by1;
                        cbx2[tid] = bx2; cby2[tid] = by2;
                        car[tid] = ba; csc[tid] = s; cid[tid] = idx;
                    }
                }
                sflag[tid] = surv ? 1 : 0;
                __syncthreads();

                // warp 0 resolves intra-batch order serially
                if (tid < 32) {
                    int kcl = kcount;
                    int kc0 = kcl;
                    for (int q = 0; q < NMS_BS; q++) {
                        if (kcl >= MAXKEEP) break;
                        if (!sflag[q]) continue;
                        float bx1 = cbx1[q], by1 = cby1[q];
                        float bx2 = cbx2[q], by2 = cby2[q], ba = car[q];
                        bool supp = false;
                        for (int j = kc0 + tid; j < kcl; j += 32) {
                            float ix1 = fmaxf(kx1[j], bx1), iy1 = fmaxf(ky1a[j], by1);
                            float ix2 = fminf(kx2[j], bx2), iy2 = fminf(ky2a[j], by2);
                            float inter = fmaxf(ix2 - ix1, 0.0f) * fmaxf(iy2 - iy1, 0.0f);
                            float iou = inter / ((kar[j] + ba) - inter);
                            if (iou > 0.5f) supp = true;
                        }
                        supp = __any_sync(0xFFFFFFFFu, supp);
                        if (!supp) {
                            if (tid == 0) {
                                kx1[kcl] = bx1; ky1a[kcl] = by1;
                                kx2[kcl] = bx2; ky2a[kcl] = by2;
                                kar[kcl] = ba; ksc[kcl] = csc[q]; kid[kcl] = cid[q];
                            }
                            kcl++;
                            __syncwarp();
                        }
                    }
                    if (tid == 0) kcount = kcl;
                }
                __syncthreads();
            }
        }
        hi = wlo;
        __syncthreads();
    }
    __syncthreads();

    // scatter kept entries into output
    int kc = kcount;
    for (int t = tid; t < kc; t += NMS_BS) {
        int i = kid[t];
        out[c * AN + i] = ksc[t];
        out[CA + c * AN + i] = (float)c;
        int b = 2 * CA + (c * AN + i) * 4;
        out[b + 0] = kx1[t];
        out[b + 1] = ky1a[t];
        out[b + 2] = kx2[t];
        out[b + 3] = ky2a[t];
        out[6 * CA + c * AN + i] = 1.0f;
    }
}

// ---------------------------------------------------------------------------
extern "C" void kernel_launch(void* const* d_in, const int* in_sizes, int n_in,
                              void* d_out, int out_size) {
    const float* classification = (const float*)d_in[0];  // [1, A, C]
    const float* regression = (const float*)d_in[1];      // [1, A, 4]
    const float* anchors = (const float*)d_in[2];         // [A, 4]
    float* out = (float*)d_out;

    decode_kernel<<<(AN + 255) / 256, 256>>>(anchors, regression);

    dim3 tb(32, 32);
    dim3 tg((AN + 31) / 32, (NC + 31) / 32);
    transpose_kernel<<<tg, tb>>>(classification);

    int n4 = out_size / 4;
    fill_kernel<<<2048, 256>>>((float4*)out, n4);

    nms_kernel<<<NC, NMS_BS>>>(out);
}

// round 4
// speedup vs baseline: 1.9066x; 1.9066x over previous
#include <cuda_runtime.h>

#define AN 76725
#define NC 80
#define CA (AN * NC)
#define CAP 2048
#define MAXKEEP 200
#define IMGF 640.0f
#define T_HI 0.99f
#define T_LO 0.97f
#define BS 256
#define FULLW 0xFFFFFFFFu

// Scratch (device globals: no allocation allowed)
__device__ float g_boxes[AN * 4];  // decoded boxes
__device__ float g_area[AN];
__device__ unsigned long long g_cand[2][NC][CAP];  // per-tier per-class (score,idx) keys
__device__ int g_cnt[2][NC];

// ---------------------------------------------------------------------------
// Decode + clip boxes, precompute areas; also zero candidate counters
// ---------------------------------------------------------------------------
__global__ void decode_kernel(const float* __restrict__ anchors,
                              const float* __restrict__ reg) {
    int i = blockIdx.x * blockDim.x + threadIdx.x;
    if (i < 2 * NC) ((int*)g_cnt)[i] = 0;
    if (i >= AN) return;
    float a0 = anchors[i * 4 + 0], a1 = anchors[i * 4 + 1];
    float a2 = anchors[i * 4 + 2], a3 = anchors[i * 4 + 3];
    float r0 = reg[i * 4 + 0], r1 = reg[i * 4 + 1];
    float r2 = reg[i * 4 + 2], r3 = reg[i * 4 + 3];
    float aw = a2 - a0, ah = a3 - a1;
    float ax = a0 + 0.5f * aw, ay = a1 + 0.5f * ah;
    float cx = ax + r0 * 0.1f * aw;
    float cy = ay + r1 * 0.1f * ah;
    float w = aw * expf(r2 * 0.2f);
    float h = ah * expf(r3 * 0.2f);
    float x1 = fminf(fmaxf(cx - 0.5f * w, 0.0f), IMGF);
    float y1 = fminf(fmaxf(cy - 0.5f * h, 0.0f), IMGF);
    float x2 = fminf(fmaxf(cx + 0.5f * w, 0.0f), IMGF);
    float y2 = fminf(fmaxf(cy + 0.5f * h, 0.0f), IMGF);
    g_boxes[i * 4 + 0] = x1;
    g_boxes[i * 4 + 1] = y1;
    g_boxes[i * 4 + 2] = x2;
    g_boxes[i * 4 + 3] = y2;
    g_area[i] = (x2 - x1) * (y2 - y1);
}

// ---------------------------------------------------------------------------
// Full-chip gather of high-score candidates, directly from [A, C] layout
// ---------------------------------------------------------------------------
__global__ void gather_kernel(const float* __restrict__ cls) {
    int idx = blockIdx.x * blockDim.x + threadIdx.x;
    if (idx >= CA) return;
    float s = cls[idx];
    if (s > T_LO) {
        int c = idx % NC;
        int a = idx / NC;
        int tier = (s > T_HI) ? 0 : 1;
        int p = atomicAdd(&g_cnt[tier][c], 1);
        if (p < CAP)
            g_cand[tier][c][p] = ((unsigned long long)__float_as_uint(s) << 32) |
                                 (unsigned long long)(0xFFFFFFFFu - (unsigned)a);
    }
}

// ---------------------------------------------------------------------------
// Fill defaults: scores=0, labels=-1, boxes=0, keep=0 (float4 stores)
// ---------------------------------------------------------------------------
__global__ void fill_kernel(float4* __restrict__ out4, int n4) {
    const int ca4 = CA / 4;
    int stride = gridDim.x * blockDim.x;
    for (int i = blockIdx.x * blockDim.x + threadIdx.x; i < n4; i += stride) {
        float v = (i >= ca4 && i < 2 * ca4) ? -1.0f : 0.0f;
        out4[i] = make_float4(v, v, v, v);
    }
}

// ---------------------------------------------------------------------------
// Per-class NMS: one block per class. Sort gathered candidates, then a
// conflict-bitmask batched greedy walk. Exact fallback if insufficient.
// ---------------------------------------------------------------------------
__global__ __launch_bounds__(BS) void nms_kernel(const float* __restrict__ cls,
                                                 float* __restrict__ out) {
    const int c = blockIdx.x;
    const int tid = threadIdx.x;
    const int lane = tid & 31, wid = tid >> 5;

    __shared__ unsigned long long skey[CAP];                     // 16KB (aliased by fallback)
    __shared__ unsigned cmask[BS][8];                            // 8KB conflict matrix
    __shared__ float bx1[BS], by1[BS], bx2[BS], by2[BS], bar_[BS], bsc[BS];
    __shared__ int bidx[BS];
    __shared__ float kx1[MAXKEEP], ky1[MAXKEEP], kx2[MAXKEEP], ky2[MAXKEEP];
    __shared__ float kar[MAXKEEP], ksc[MAXKEEP];
    __shared__ int kid[MAXKEEP];
    __shared__ unsigned aliveK[8];
    __shared__ int kcount;
    __shared__ unsigned long long redbuf[BS];                    // fallback argmax

    if (tid == 0) kcount = 0;
    __syncthreads();

    bool ok = true;
    for (int tier = 0; tier < 2; tier++) {
        if (kcount >= MAXKEEP) break;
        int n = g_cnt[tier][c];
        if (n > CAP) { ok = false; break; }
        if (n == 0) continue;

        // load + pad + bitonic sort (descending)
        for (int i = tid; i < n; i += BS) skey[i] = g_cand[tier][c][i];
        int m = 1;
        while (m < n) m <<= 1;
        for (int i = n + tid; i < m; i += BS) skey[i] = 0ULL;
        __syncthreads();
        for (int k = 2; k <= m; k <<= 1) {
            for (int j = k >> 1; j > 0; j >>= 1) {
                for (int i = tid; i < m; i += BS) {
                    int ixj = i ^ j;
                    if (ixj > i) {
                        bool desc = ((i & k) == 0);
                        unsigned long long A = skey[i], B2 = skey[ixj];
                        if (desc ? (A < B2) : (A > B2)) { skey[i] = B2; skey[ixj] = A; }
                    }
                }
                __syncthreads();
            }
        }

        // batched conflict-mask greedy walk
        for (int base = 0; base < n; base += BS) {
            if (kcount >= MAXKEEP) break;
            int nb = min(BS, n - base);
            bool have = tid < nb;
            float mx1 = 0, my1 = 0, mx2 = 0, my2 = 0, ma = 0;
            if (have) {
                unsigned long long key = skey[base + tid];
                float s = __uint_as_float((unsigned)(key >> 32));
                int idx = (int)(0xFFFFFFFFu - (unsigned)key);
                mx1 = g_boxes[idx * 4 + 0];
                my1 = g_boxes[idx * 4 + 1];
                mx2 = g_boxes[idx * 4 + 2];
                my2 = g_boxes[idx * 4 + 3];
                ma = g_area[idx];
                bx1[tid] = mx1; by1[tid] = my1; bx2[tid] = mx2; by2[tid] = my2;
                bar_[tid] = ma; bsc[tid] = s; bidx[tid] = idx;
            }
            __syncthreads();

            // phase 1a: survival vs already-kept list
            int kc = kcount;
            bool alive = have;
            if (alive) {
                for (int j = 0; j < kc; j++) {
                    float ix1 = fmaxf(kx1[j], mx1), iy1 = fmaxf(ky1[j], my1);
                    float ix2 = fminf(kx2[j], mx2), iy2 = fminf(ky2[j], my2);
                    float inter = fmaxf(ix2 - ix1, 0.0f) * fmaxf(iy2 - iy1, 0.0f);
                    float iou = inter / ((kar[j] + ma) - inter);
                    if (iou > 0.5f) { alive = false; break; }
                }
            }
            unsigned ab = __ballot_sync(FULLW, alive);
            if (lane == 0) aliveK[wid] = ab;

            // phase 1b: in-batch conflict matrix via ballots (column j, warp wid)
            for (int j = 0; j < nb; j++) {
                float jx1 = bx1[j], jy1 = by1[j], jx2 = bx2[j], jy2 = by2[j], ja = bar_[j];
                bool cf = false;
                if (have && tid != j) {
                    float ix1 = fmaxf(jx1, mx1), iy1 = fmaxf(jy1, my1);
                    float ix2 = fminf(jx2, mx2), iy2 = fminf(jy2, my2);
                    float inter = fmaxf(ix2 - ix1, 0.0f) * fmaxf(iy2 - iy1, 0.0f);
                    float iou = inter / ((ja + ma) - inter);
                    cf = iou > 0.5f;
                }
                unsigned bits = __ballot_sync(FULLW, cf);
                if (lane == 0) cmask[j][wid] = bits;
            }
            __syncthreads();

            // phase 2: warp 0 resolves order with register bitmask
            if (tid < 32) {
                unsigned aw = (lane < 8) ? aliveK[lane] : 0u;
                int kcl = kcount;
                for (int q = 0; q < nb; q++) {
                    int w = q >> 5, b = q & 31;
                    bool bit = (lane == w) && ((aw >> b) & 1u);
                    unsigned v = __ballot_sync(FULLW, bit);
                    if (v) {
                        if (lane == 0) {
                            kx1[kcl] = bx1[q]; ky1[kcl] = by1[q];
                            kx2[kcl] = bx2[q]; ky2[kcl] = by2[q];
                            kar[kcl] = bar_[q]; ksc[kcl] = bsc[q]; kid[kcl] = bidx[q];
                        }
                        if (lane < 8) aw &= ~cmask[q][lane];
                        kcl++;
                        if (kcl >= MAXKEEP) break;
                    }
                }
                __syncwarp();
                if (lane == 0) kcount = kcl;
            }
            __syncthreads();
        }
    }
    __syncthreads();

    // Exact fallback (never triggered for this data): from-scratch serial greedy
    if (!ok || kcount < MAXKEEP) {
        unsigned* supp = (unsigned*)skey;
        const int NW = (AN + 31) / 32;
        for (int w2 = tid; w2 < NW; w2 += BS) supp[w2] = 0u;
        if (tid == 0) kcount = 0;
        __syncthreads();
        for (int it = 0; it < MAXKEEP; it++) {
            unsigned long long best = 0ULL;
            for (int i = tid; i < AN; i += BS) {
                if (!((supp[i >> 5] >> (i & 31)) & 1u)) {
                    float s = cls[i * NC + c];
                    if (s > 0.1f) {
                        unsigned long long k =
                            ((unsigned long long)__float_as_uint(s) << 32) |
                            (unsigned long long)(0xFFFFFFFFu - (unsigned)i);
                        if (k > best) best = k;
                    }
                }
            }
            redbuf[tid] = best;
            __syncthreads();
            for (int off = BS / 2; off > 0; off >>= 1) {
                if (tid < off && redbuf[tid + off] > redbuf[tid]) redbuf[tid] = redbuf[tid + off];
                __syncthreads();
            }
            unsigned long long bk = redbuf[0];
            __syncthreads();
            if (bk == 0ULL) break;
            int bi = (int)(0xFFFFFFFFu - (unsigned)bk);
            float s = __uint_as_float((unsigned)(bk >> 32));
            float zx1 = g_boxes[bi * 4 + 0], zy1 = g_boxes[bi * 4 + 1];
            float zx2 = g_boxes[bi * 4 + 2], zy2 = g_boxes[bi * 4 + 3];
            float za = g_area[bi];
            if (tid == 0) {
                int kc2 = kcount;
                kx1[kc2] = zx1; ky1[kc2] = zy1; kx2[kc2] = zx2; ky2[kc2] = zy2;
                kar[kc2] = za; ksc[kc2] = s; kid[kc2] = bi;
                kcount = kc2 + 1;
            }
            for (int i = tid; i < AN; i += BS) {
                float ix1 = fmaxf(zx1, g_boxes[i * 4 + 0]);
                float iy1 = fmaxf(zy1, g_boxes[i * 4 + 1]);
                float ix2 = fminf(zx2, g_boxes[i * 4 + 2]);
                float iy2 = fminf(zy2, g_boxes[i * 4 + 3]);
                float inter = fmaxf(ix2 - ix1, 0.0f) * fmaxf(iy2 - iy1, 0.0f);
                float iou = inter / ((za + g_area[i]) - inter);
                if (iou > 0.5f || i == bi) atomicOr(&supp[i >> 5], 1u << (i & 31));
            }
            __syncthreads();
        }
        __syncthreads();
    }

    // scatter kept entries into output
    int kc = kcount;
    for (int t = tid; t < kc; t += BS) {
        int i = kid[t];
        out[c * AN + i] = ksc[t];
        out[CA + c * AN + i] = (float)c;
        int b = 2 * CA + (c * AN + i) * 4;
        out[b + 0] = kx1[t];
        out[b + 1] = ky1[t];
        out[b + 2] = kx2[t];
        out[b + 3] = ky2[t];
        out[6 * CA + c * AN + i] = 1.0f;
    }
}

// ---------------------------------------------------------------------------
extern "C" void kernel_launch(void* const* d_in, const int* in_sizes, int n_in,
                              void* d_out, int out_size) {
    const float* classification = (const float*)d_in[0];  // [1, A, C]
    const float* regression = (const float*)d_in[1];      // [1, A, 4]
    const float* anchors = (const float*)d_in[2];         // [A, 4]
    float* out = (float*)d_out;

    decode_kernel<<<(AN + 255) / 256, 256>>>(anchors, regression);
    gather_kernel<<<(CA + 255) / 256, 256>>>(classification);

    int n4 = out_size / 4;
    fill_kernel<<<2048, 256>>>((float4*)out, n4);

    nms_kernel<<<NC, BS>>>(classification, out);
}

// round 5
// speedup vs baseline: 3.3958x; 1.7811x over previous
#include <cuda_runtime.h>

#define AN 76725
#define NC 80
#define CA (AN * NC)
#define CAP 2048
#define MAXKEEP 200
#define IMGF 640.0f
#define T_HI 0.99f
#define T_LO 0.97f
#define NT 1024
#define FULLW 0xFFFFFFFFu

// Scratch (device globals: no allocation allowed)
__device__ float g_boxes[AN * 4];  // decoded boxes
__device__ float g_area[AN];
__device__ unsigned long long g_cand[2][NC][CAP];  // per-tier per-class (score,idx) keys
__device__ int g_cnt[2][NC];

// ---------------------------------------------------------------------------
__global__ void decode_kernel(const float* __restrict__ anchors,
                              const float* __restrict__ reg) {
    int i = blockIdx.x * blockDim.x + threadIdx.x;
    if (i < 2 * NC) ((int*)g_cnt)[i] = 0;
    if (i >= AN) return;
    float a0 = anchors[i * 4 + 0], a1 = anchors[i * 4 + 1];
    float a2 = anchors[i * 4 + 2], a3 = anchors[i * 4 + 3];
    float r0 = reg[i * 4 + 0], r1 = reg[i * 4 + 1];
    float r2 = reg[i * 4 + 2], r3 = reg[i * 4 + 3];
    float aw = a2 - a0, ah = a3 - a1;
    float ax = a0 + 0.5f * aw, ay = a1 + 0.5f * ah;
    float cx = ax + r0 * 0.1f * aw;
    float cy = ay + r1 * 0.1f * ah;
    float w = aw * expf(r2 * 0.2f);
    float h = ah * expf(r3 * 0.2f);
    float x1 = fminf(fmaxf(cx - 0.5f * w, 0.0f), IMGF);
    float y1 = fminf(fmaxf(cy - 0.5f * h, 0.0f), IMGF);
    float x2 = fminf(fmaxf(cx + 0.5f * w, 0.0f), IMGF);
    float y2 = fminf(fmaxf(cy + 0.5f * h, 0.0f), IMGF);
    g_boxes[i * 4 + 0] = x1;
    g_boxes[i * 4 + 1] = y1;
    g_boxes[i * 4 + 2] = x2;
    g_boxes[i * 4 + 3] = y2;
    g_area[i] = (x2 - x1) * (y2 - y1);
}

// ---------------------------------------------------------------------------
__global__ void gather_kernel(const float* __restrict__ cls) {
    int idx = blockIdx.x * blockDim.x + threadIdx.x;
    if (idx >= CA) return;
    float s = cls[idx];
    if (s > T_LO) {
        int c = idx % NC;
        int a = idx / NC;
        int tier = (s > T_HI) ? 0 : 1;
        int p = atomicAdd(&g_cnt[tier][c], 1);
        if (p < CAP)
            g_cand[tier][c][p] = ((unsigned long long)__float_as_uint(s) << 32) |
                                 (unsigned long long)(0xFFFFFFFFu - (unsigned)a);
    }
}

// ---------------------------------------------------------------------------
__global__ void fill_kernel(float4* __restrict__ out4, int n4) {
    const int ca4 = CA / 4;
    int stride = gridDim.x * blockDim.x;
    for (int i = blockIdx.x * blockDim.x + threadIdx.x; i < n4; i += stride) {
        float v = (i >= ca4 && i < 2 * ca4) ? -1.0f : 0.0f;
        out4[i] = make_float4(v, v, v, v);
    }
}

// ---------------------------------------------------------------------------
// Per-class NMS, 1024 threads/block. Sort gathered candidates, build in-batch
// conflict matrix, resolve greedy order via conflict-graph (deferred-only
// serial pass). Exact from-scratch fallback if insufficient candidates.
// ---------------------------------------------------------------------------
__global__ __launch_bounds__(NT) void nms_kernel(const float* __restrict__ cls,
                                                 float* __restrict__ out) {
    const int c = blockIdx.x;
    const int tid = threadIdx.x;
    const int lane = tid & 31, wid = tid >> 5;

    __shared__ unsigned long long skey[CAP];  // 16KB (fallback: supp bitmap)
    __shared__ unsigned cmask[256][8];        // 8KB  (fallback: redbuf)
    __shared__ float bx1[256], by1[256], bx2[256], by2[256], bar_[256], bsc[256];
    __shared__ int bidx[256];
    __shared__ float kx1[MAXKEEP], ky1[MAXKEEP], kx2[MAXKEEP], ky2[MAXKEEP];
    __shared__ float kar[MAXKEEP], ksc[MAXKEEP];
    __shared__ int kid[MAXKEEP];
    __shared__ unsigned confParts[32];
    __shared__ unsigned aliveK[8], kmw[8], dmw[8];
    __shared__ int kcount;

    if (tid == 0) kcount = 0;
    __syncthreads();

    bool ok = true;
    for (int tier = 0; tier < 2; tier++) {
        if (kcount >= MAXKEEP) break;
        int n = g_cnt[tier][c];
        if (n > CAP) { ok = false; break; }
        if (n == 0) continue;

        // ---- load + pad + bitonic sort descending ----
        for (int i = tid; i < n; i += NT) skey[i] = g_cand[tier][c][i];
        int m = 1;
        while (m < n) m <<= 1;
        for (int i = n + tid; i < m; i += NT) skey[i] = 0ULL;
        __syncthreads();
        for (int k = 2; k <= m; k <<= 1) {
            for (int j = k >> 1; j > 0; j >>= 1) {
                for (int i = tid; i < m; i += NT) {
                    int ixj = i ^ j;
                    if (ixj > i) {
                        bool desc = ((i & k) == 0);
                        unsigned long long A = skey[i], B2 = skey[ixj];
                        if (desc ? (A < B2) : (A > B2)) { skey[i] = B2; skey[ixj] = A; }
                    }
                }
                __syncthreads();
            }
        }

        // ---- batched walk ----
        for (int base = 0; base < n; base += 256) {
            if (kcount >= MAXKEEP) break;
            int nb = min(256, n - base);

            // load batch (threads 0..255)
            if (tid < nb) {
                unsigned long long key = skey[base + tid];
                float s = __uint_as_float((unsigned)(key >> 32));
                int idx = (int)(0xFFFFFFFFu - (unsigned)key);
                bx1[tid] = g_boxes[idx * 4 + 0];
                by1[tid] = g_boxes[idx * 4 + 1];
                bx2[tid] = g_boxes[idx * 4 + 2];
                by2[tid] = g_boxes[idx * 4 + 3];
                bar_[tid] = g_area[idx];
                bsc[tid] = s;
                bidx[tid] = idx;
            }
            __syncthreads();

            int i = tid & 255;
            int g = tid >> 8;  // 0..3
            bool have = i < nb;
            float mx1 = 0, my1 = 0, mx2 = 0, my2 = 0, ma = 0;
            if (have) {
                mx1 = bx1[i]; my1 = by1[i]; mx2 = bx2[i]; my2 = by2[i]; ma = bar_[i];
            }

            // phase 1a: conflict vs kept list, 4-way split per candidate
            int kc = kcount;
            bool cfk = false;
            if (have) {
                for (int j = g; j < kc; j += 4) {
                    float ix1 = fmaxf(kx1[j], mx1), iy1 = fmaxf(ky1[j], my1);
                    float ix2 = fminf(kx2[j], mx2), iy2 = fminf(ky2[j], my2);
                    float inter = fmaxf(ix2 - ix1, 0.0f) * fmaxf(iy2 - iy1, 0.0f);
                    float iou = inter / ((kar[j] + ma) - inter);
                    if (iou > 0.5f) { cfk = true; break; }
                }
            }
            unsigned cb = __ballot_sync(FULLW, cfk);
            if (lane == 0) confParts[wid] = cb;
            __syncthreads();
            if (tid < 8) {
                int r = nb - tid * 32;
                unsigned hv = r >= 32 ? FULLW : (r <= 0 ? 0u : ((1u << r) - 1u));
                aliveK[tid] = hv & ~(confParts[tid] | confParts[tid + 8] |
                                     confParts[tid + 16] | confParts[tid + 24]);
            }
            __syncthreads();

            // phase 1b: in-batch conflict matrix, 4 columns per ballot round
            for (int jb = 0; jb < 256; jb += 4) {
                int j = jb + g;
                bool cf = false;
                if (j < nb && have && i != j) {
                    float ix1 = fmaxf(bx1[j], mx1), iy1 = fmaxf(by1[j], my1);
                    float ix2 = fminf(bx2[j], mx2), iy2 = fminf(by2[j], my2);
                    float inter = fmaxf(ix2 - ix1, 0.0f) * fmaxf(iy2 - iy1, 0.0f);
                    float iou = inter / ((bar_[j] + ma) - inter);
                    cf = iou > 0.5f;
                }
                unsigned bits = __ballot_sync(FULLW, cf);
                if (lane == 0 && j < nb) cmask[j][wid & 7] = bits;
            }
            __syncthreads();

            // trivial/deferred classification (threads 0..255)
            {
                bool trivial = false, deferred = false;
                if (tid < 256) {
                    bool aliveMe = (aliveK[wid] >> lane) & 1u;
                    if (aliveMe) {
                        unsigned conf = 0;
                        #pragma unroll
                        for (int w = 0; w < 8; w++) {
                            unsigned below = (w < wid) ? FULLW
                                           : (w == wid ? ((1u << lane) - 1u) : 0u);
                            conf |= cmask[tid][w] & aliveK[w] & below;
                        }
                        trivial = (conf == 0);
                        deferred = !trivial;
                    }
                }
                unsigned tb = __ballot_sync(FULLW, trivial);
                unsigned db = __ballot_sync(FULLW, deferred);
                if (tid < 256 && lane == 0) { kmw[wid] = tb; dmw[wid] = db; }
            }
            __syncthreads();

            // warp 0: resolve deferred serially, then truncate to rem
            if (tid < 32) {
                unsigned kw = (lane < 8) ? kmw[lane] : 0u;
                for (int w = 0; w < 8; w++) {
                    unsigned dbits = dmw[w];
                    while (dbits) {
                        int b = __ffs(dbits) - 1;
                        dbits &= dbits - 1;
                        int q = w * 32 + b;
                        unsigned below = (lane < w) ? FULLW
                                       : (lane == w ? ((1u << b) - 1u) : 0u);
                        unsigned rowv = (lane < 8) ? cmask[q][lane] : 0u;
                        bool sup = (rowv & kw & below) != 0u;
                        sup = __any_sync(FULLW, sup);
                        if (!sup && lane == w) kw |= (1u << b);
                    }
                }
                if (lane < 8) kmw[lane] = kw;
                __syncwarp();
                if (lane == 0) {
                    int rem = MAXKEEP - kcount;
                    int acc = 0;
                    for (int w = 0; w < 8; w++) {
                        unsigned v = kmw[w];
                        int p = __popc(v);
                        if (acc + p > rem) {
                            int need = rem - acc;
                            // keep lowest `need` set bits
                            while (p > need) {
                                v &= ~(0x80000000u >> __clz(v));
                                p--;
                            }
                            kmw[w] = v;
                            for (int w2 = w + 1; w2 < 8; w2++) kmw[w2] = 0u;
                            acc = rem;
                            break;
                        }
                        acc += p;
                    }
                }
            }
            __syncthreads();

            // append kept (threads 0..255), prefix via popcounts
            int kc0 = kcount;
            if (tid < 256 && ((kmw[wid] >> lane) & 1u)) {
                int pos = kc0;
                for (int w = 0; w < wid; w++) pos += __popc(kmw[w]);
                pos += __popc(kmw[wid] & ((1u << lane) - 1u));
                kx1[pos] = bx1[tid]; ky1[pos] = by1[tid];
                kx2[pos] = bx2[tid]; ky2[pos] = by2[tid];
                kar[pos] = bar_[tid]; ksc[pos] = bsc[tid]; kid[pos] = bidx[tid];
            }
            __syncthreads();
            if (tid == 0) {
                int t = 0;
                for (int w = 0; w < 8; w++) t += __popc(kmw[w]);
                kcount = kc0 + t;
            }
            __syncthreads();
        }
    }
    __syncthreads();

    // ---- Exact fallback (never triggered for this data) ----
    if (!ok || kcount < MAXKEEP) {
        unsigned* supp = (unsigned*)skey;                     // 9.6KB of 16KB
        unsigned long long* redbuf = (unsigned long long*)cmask;  // 8KB exactly
        const int NW = (AN + 31) / 32;
        for (int w2 = tid; w2 < NW; w2 += NT) supp[w2] = 0u;
        if (tid == 0) kcount = 0;
        __syncthreads();
        for (int it = 0; it < MAXKEEP; it++) {
            unsigned long long best = 0ULL;
            for (int i = tid; i < AN; i += NT) {
                if (!((supp[i >> 5] >> (i & 31)) & 1u)) {
                    float s = cls[i * NC + c];
                    if (s > 0.1f) {
                        unsigned long long k =
                            ((unsigned long long)__float_as_uint(s) << 32) |
                            (unsigned long long)(0xFFFFFFFFu - (unsigned)i);
                        if (k > best) best = k;
                    }
                }
            }
            redbuf[tid] = best;
            __syncthreads();
            for (int off = NT / 2; off > 0; off >>= 1) {
                if (tid < off && redbuf[tid + off] > redbuf[tid]) redbuf[tid] = redbuf[tid + off];
                __syncthreads();
            }
            unsigned long long bk = redbuf[0];
            __syncthreads();
            if (bk == 0ULL) break;
            int bi = (int)(0xFFFFFFFFu - (unsigned)bk);
            float s = __uint_as_float((unsigned)(bk >> 32));
            float zx1 = g_boxes[bi * 4 + 0], zy1 = g_boxes[bi * 4 + 1];
            float zx2 = g_boxes[bi * 4 + 2], zy2 = g_boxes[bi * 4 + 3];
            float za = g_area[bi];
            if (tid == 0) {
                int kc2 = kcount;
                kx1[kc2] = zx1; ky1[kc2] = zy1; kx2[kc2] = zx2; ky2[kc2] = zy2;
                kar[kc2] = za; ksc[kc2] = s; kid[kc2] = bi;
                kcount = kc2 + 1;
            }
            for (int i = tid; i < AN; i += NT) {
                float ix1 = fmaxf(zx1, g_boxes[i * 4 + 0]);
                float iy1 = fmaxf(zy1, g_boxes[i * 4 + 1]);
                float ix2 = fminf(zx2, g_boxes[i * 4 + 2]);
                float iy2 = fminf(zy2, g_boxes[i * 4 + 3]);
                float inter = fmaxf(ix2 - ix1, 0.0f) * fmaxf(iy2 - iy1, 0.0f);
                float iou = inter / ((za + g_area[i]) - inter);
                if (iou > 0.5f || i == bi) atomicOr(&supp[i >> 5], 1u << (i & 31));
            }
            __syncthreads();
        }
        __syncthreads();
    }

    // ---- scatter kept entries into output ----
    int kc = kcount;
    for (int t = tid; t < kc; t += NT) {
        int i = kid[t];
        out[c * AN + i] = ksc[t];
        out[CA + c * AN + i] = (float)c;
        int b = 2 * CA + (c * AN + i) * 4;
        out[b + 0] = kx1[t];
        out[b + 1] = ky1[t];
        out[b + 2] = kx2[t];
        out[b + 3] = ky2[t];
        out[6 * CA + c * AN + i] = 1.0f;
    }
}

// ---------------------------------------------------------------------------
extern "C" void kernel_launch(void* const* d_in, const int* in_sizes, int n_in,
                              void* d_out, int out_size) {
    const float* classification = (const float*)d_in[0];  // [1, A, C]
    const float* regression = (const float*)d_in[1];      // [1, A, 4]
    const float* anchors = (const float*)d_in[2];         // [A, 4]
    float* out = (float*)d_out;

    decode_kernel<<<(AN + 255) / 256, 256>>>(anchors, regression);
    gather_kernel<<<(CA + 255) / 256, 256>>>(classification);

    int n4 = out_size / 4;
    fill_kernel<<<4096, 256>>>((float4*)out, n4);

    nms_kernel<<<NC, NT>>>(classification, out);
}

// round 6
// speedup vs baseline: 3.6250x; 1.0675x over previous
#include <cuda_runtime.h>

#define AN 76725
#define NC 80
#define CA (AN * NC)
#define CAP 2048
#define MAXKEEP 200
#define IMGF 640.0f
#define T_HI 0.99f
#define T_LO 0.97f
#define NT 1024
#define NB 64
#define FULLW 0xFFFFFFFFu

// Scratch (device globals: no allocation allowed)
__device__ float g_boxes[AN * 4];  // decoded boxes
__device__ float g_area[AN];
__device__ unsigned long long g_cand[2][NC][CAP];  // per-tier per-class (score,idx) keys
__device__ int g_cnt[2][NC];

// ---------------------------------------------------------------------------
__global__ void decode_kernel(const float* __restrict__ anchors,
                              const float* __restrict__ reg) {
    int i = blockIdx.x * blockDim.x + threadIdx.x;
    if (i < 2 * NC) ((int*)g_cnt)[i] = 0;
    if (i >= AN) return;
    float a0 = anchors[i * 4 + 0], a1 = anchors[i * 4 + 1];
    float a2 = anchors[i * 4 + 2], a3 = anchors[i * 4 + 3];
    float r0 = reg[i * 4 + 0], r1 = reg[i * 4 + 1];
    float r2 = reg[i * 4 + 2], r3 = reg[i * 4 + 3];
    float aw = a2 - a0, ah = a3 - a1;
    float ax = a0 + 0.5f * aw, ay = a1 + 0.5f * ah;
    float cx = ax + r0 * 0.1f * aw;
    float cy = ay + r1 * 0.1f * ah;
    float w = aw * expf(r2 * 0.2f);
    float h = ah * expf(r3 * 0.2f);
    float x1 = fminf(fmaxf(cx - 0.5f * w, 0.0f), IMGF);
    float y1 = fminf(fmaxf(cy - 0.5f * h, 0.0f), IMGF);
    float x2 = fminf(fmaxf(cx + 0.5f * w, 0.0f), IMGF);
    float y2 = fminf(fmaxf(cy + 0.5f * h, 0.0f), IMGF);
    g_boxes[i * 4 + 0] = x1;
    g_boxes[i * 4 + 1] = y1;
    g_boxes[i * 4 + 2] = x2;
    g_boxes[i * 4 + 3] = y2;
    g_area[i] = (x2 - x1) * (y2 - y1);
}

// ---------------------------------------------------------------------------
__global__ void gather_kernel(const float* __restrict__ cls) {
    int idx = blockIdx.x * blockDim.x + threadIdx.x;
    if (idx >= CA) return;
    float s = cls[idx];
    if (s > T_LO) {
        int c = idx % NC;
        int a = idx / NC;
        int tier = (s > T_HI) ? 0 : 1;
        int p = atomicAdd(&g_cnt[tier][c], 1);
        if (p < CAP)
            g_cand[tier][c][p] = ((unsigned long long)__float_as_uint(s) << 32) |
                                 (unsigned long long)(0xFFFFFFFFu - (unsigned)a);
    }
}

// ---------------------------------------------------------------------------
// -1.0f fill for the labels region only (zeros come from cudaMemsetAsync)
__global__ void label_kernel(float4* __restrict__ out4) {
    int i = blockIdx.x * blockDim.x + threadIdx.x;
    if (i < CA / 4) out4[i] = make_float4(-1.0f, -1.0f, -1.0f, -1.0f);
}

// ---------------------------------------------------------------------------
// Per-class NMS, 1024 threads/block, 64-candidate batches with uint64 masks.
// ---------------------------------------------------------------------------
__global__ __launch_bounds__(NT) void nms_kernel(const float* __restrict__ cls,
                                                 float* __restrict__ out) {
    const int c = blockIdx.x;
    const int tid = threadIdx.x;
    const int lane = tid & 31, wid = tid >> 5;

    __shared__ unsigned long long skey[CAP];        // 16KB (fallback: supp bitmap)
    __shared__ unsigned long long cmask64[NB];      // conflict rows (symmetric)
    __shared__ float4 bbox[NB];
    __shared__ float bar_[NB], bsc[NB];
    __shared__ int bidx[NB];
    __shared__ float4 kbox[MAXKEEP];
    __shared__ float kar[MAXKEEP], ksc[MAXKEEP];
    __shared__ int kid[MAXKEEP];
    __shared__ unsigned confParts[32];
    __shared__ unsigned long long alive64_s, km64_s;
    __shared__ unsigned long long red32[32];        // fallback warp-reduce
    __shared__ int kcount;

    unsigned* cmW = (unsigned*)cmask64;
    unsigned* kmW = (unsigned*)&km64_s;

    if (tid == 0) kcount = 0;
    __syncthreads();

    bool ok = true;
    for (int tier = 0; tier < 2; tier++) {
        if (kcount >= MAXKEEP) break;
        int n = g_cnt[tier][c];
        if (n > CAP) { ok = false; break; }
        if (n == 0) continue;

        // ---- load + pad + bitonic sort descending ----
        for (int i = tid; i < n; i += NT) skey[i] = g_cand[tier][c][i];
        int m = 1;
        while (m < n) m <<= 1;
        for (int i = n + tid; i < m; i += NT) skey[i] = 0ULL;
        __syncthreads();
        for (int k = 2; k <= m; k <<= 1) {
            for (int j = k >> 1; j > 0; j >>= 1) {
                for (int i = tid; i < m; i += NT) {
                    int ixj = i ^ j;
                    if (ixj > i) {
                        bool desc = ((i & k) == 0);
                        unsigned long long A = skey[i], B2 = skey[ixj];
                        if (desc ? (A < B2) : (A > B2)) { skey[i] = B2; skey[ixj] = A; }
                    }
                }
                __syncthreads();
            }
        }

        // ---- batched walk, NB=64 ----
        for (int base = 0; base < n; base += NB) {
            if (kcount >= MAXKEEP) break;
            int nb = min(NB, n - base);

            if (tid < nb) {
                unsigned long long key = skey[base + tid];
                float s = __uint_as_float((unsigned)(key >> 32));
                int idx = (int)(0xFFFFFFFFu - (unsigned)key);
                float4 bb;
                bb.x = g_boxes[idx * 4 + 0];
                bb.y = g_boxes[idx * 4 + 1];
                bb.z = g_boxes[idx * 4 + 2];
                bb.w = g_boxes[idx * 4 + 3];
                bbox[tid] = bb;
                bar_[tid] = g_area[idx];
                bsc[tid] = s;
                bidx[tid] = idx;
            }
            __syncthreads();

            int i = tid & 63;
            int g = tid >> 6;  // 0..15
            bool have = i < nb;
            float4 mb = make_float4(0, 0, 0, 0);
            float ma = 0;
            if (have) { mb = bbox[i]; ma = bar_[i]; }

            // phase 1a: conflict vs kept list, 16-way split per candidate
            int kc = kcount;
            bool cfk = false;
            if (have) {
                for (int j = g; j < kc; j += 16) {
                    float4 kb = kbox[j];
                    float ix1 = fmaxf(kb.x, mb.x), iy1 = fmaxf(kb.y, mb.y);
                    float ix2 = fminf(kb.z, mb.z), iy2 = fminf(kb.w, mb.w);
                    float inter = fmaxf(ix2 - ix1, 0.0f) * fmaxf(iy2 - iy1, 0.0f);
                    if (inter > 0.0f) {
                        float iou = inter / ((kar[j] + ma) - inter);
                        if (iou > 0.5f) { cfk = true; break; }
                    }
                }
            }
            unsigned cb = __ballot_sync(FULLW, cfk);
            if (lane == 0) confParts[wid] = cb;
            __syncthreads();
            if (tid == 0) {
                unsigned lo = 0, hi2 = 0;
                #pragma unroll
                for (int w = 0; w < 32; w += 2) { lo |= confParts[w]; hi2 |= confParts[w + 1]; }
                unsigned long long conf = ((unsigned long long)hi2 << 32) | lo;
                unsigned long long hv = (nb >= 64) ? ~0ULL : ((1ULL << nb) - 1ULL);
                alive64_s = hv & ~conf;
            }
            __syncthreads();
            unsigned long long alive64 = alive64_s;

            // phase 1b: conflict matrix, 16 columns per ballot round (<=4 rounds)
            for (int jb = 0; jb < nb; jb += 16) {
                int j = jb + g;
                bool cf = false;
                if (have && j < nb && i != j) {
                    float4 jb4 = bbox[j];
                    float ja = bar_[j];
                    float ix1 = fmaxf(jb4.x, mb.x), iy1 = fmaxf(jb4.y, mb.y);
                    float ix2 = fminf(jb4.z, mb.z), iy2 = fminf(jb4.w, mb.w);
                    float inter = fmaxf(ix2 - ix1, 0.0f) * fmaxf(iy2 - iy1, 0.0f);
                    if (inter > 0.0f) {
                        float iou = inter / ((ja + ma) - inter);
                        cf = iou > 0.5f;
                    }
                }
                unsigned bits = __ballot_sync(FULLW, cf);
                if (lane == 0 && j < nb) cmW[2 * j + (wid & 1)] = bits;
            }
            __syncthreads();

            // classify trivial/deferred (threads 0..63 = warps 0,1)
            {
                bool trivial = false, deferred = false;
                if (tid < 64) {
                    if ((alive64 >> tid) & 1ULL) {
                        unsigned long long below = (1ULL << tid) - 1ULL;
                        unsigned long long conf = cmask64[tid] & alive64 & below;
                        trivial = (conf == 0ULL);
                        deferred = !trivial;
                    }
                }
                unsigned tb = __ballot_sync(FULLW, trivial);
                unsigned db = __ballot_sync(FULLW, deferred);
                if (lane == 0 && wid < 2) kmW[wid] = tb;
                if (lane == 1 && wid < 2) red32[wid] = db;  // stash deferred halves
            }
            __syncthreads();

            // thread 0: resolve deferred serially with 64-bit masks, truncate
            if (tid == 0) {
                unsigned long long kw = km64_s;
                unsigned long long dbits = ((unsigned long long)(unsigned)red32[1] << 32) |
                                           (unsigned)red32[0];
                while (dbits) {
                    int q = __ffsll((long long)dbits) - 1;
                    dbits &= dbits - 1ULL;
                    unsigned long long below = (1ULL << q) - 1ULL;
                    if ((cmask64[q] & kw & below) == 0ULL) kw |= (1ULL << q);
                }
                int rem = MAXKEEP - kcount;
                int p = __popcll(kw);
                while (p > rem) {
                    kw &= ~(0x8000000000000000ULL >> __clzll((long long)kw));
                    p--;
                }
                km64_s = kw;
            }
            __syncthreads();

            unsigned long long kw = km64_s;
            int kc0 = kcount;
            if (tid < 64 && ((kw >> tid) & 1ULL)) {
                int pos = kc0 + __popcll(kw & ((1ULL << tid) - 1ULL));
                kbox[pos] = bbox[tid];
                kar[pos] = bar_[tid];
                ksc[pos] = bsc[tid];
                kid[pos] = bidx[tid];
            }
            __syncthreads();
            if (tid == 0) kcount = kc0 + __popcll(kw);
            __syncthreads();
        }
    }
    __syncthreads();

    // ---- Exact fallback (never triggered for this data) ----
    if (!ok || kcount < MAXKEEP) {
        unsigned* supp = (unsigned*)skey;  // 9.6KB of 16KB
        const int NW = (AN + 31) / 32;
        for (int w2 = tid; w2 < NW; w2 += NT) supp[w2] = 0u;
        if (tid == 0) kcount = 0;
        __syncthreads();
        for (int it = 0; it < MAXKEEP; it++) {
            unsigned long long best = 0ULL;
            for (int i = tid; i < AN; i += NT) {
                if (!((supp[i >> 5] >> (i & 31)) & 1u)) {
                    float s = cls[i * NC + c];
                    if (s > 0.1f) {
                        unsigned long long k =
                            ((unsigned long long)__float_as_uint(s) << 32) |
                            (unsigned long long)(0xFFFFFFFFu - (unsigned)i);
                        if (k > best) best = k;
                    }
                }
            }
            #pragma unroll
            for (int off = 16; off > 0; off >>= 1) {
                unsigned long long o = __shfl_down_sync(FULLW, best, off);
                if (o > best) best = o;
            }
            if (lane == 0) red32[wid] = best;
            __syncthreads();
            if (tid == 0) {
                unsigned long long b2 = red32[0];
                for (int w = 1; w < 32; w++)
                    if (red32[w] > b2) b2 = red32[w];
                red32[0] = b2;
            }
            __syncthreads();
            unsigned long long bk = red32[0];
            __syncthreads();
            if (bk == 0ULL) break;
            int bi = (int)(0xFFFFFFFFu - (unsigned)bk);
            float s = __uint_as_float((unsigned)(bk >> 32));
            float zx1 = g_boxes[bi * 4 + 0], zy1 = g_boxes[bi * 4 + 1];
            float zx2 = g_boxes[bi * 4 + 2], zy2 = g_boxes[bi * 4 + 3];
            float za = g_area[bi];
            if (tid == 0) {
                int kc2 = kcount;
                kbox[kc2] = make_float4(zx1, zy1, zx2, zy2);
                kar[kc2] = za; ksc[kc2] = s; kid[kc2] = bi;
                kcount = kc2 + 1;
            }
            for (int i = tid; i < AN; i += NT) {
                float ix1 = fmaxf(zx1, g_boxes[i * 4 + 0]);
                float iy1 = fmaxf(zy1, g_boxes[i * 4 + 1]);
                float ix2 = fminf(zx2, g_boxes[i * 4 + 2]);
                float iy2 = fminf(zy2, g_boxes[i * 4 + 3]);
                float inter = fmaxf(ix2 - ix1, 0.0f) * fmaxf(iy2 - iy1, 0.0f);
                float iou = inter / ((za + g_area[i]) - inter);
                if (iou > 0.5f || i == bi) atomicOr(&supp[i >> 5], 1u << (i & 31));
            }
            __syncthreads();
        }
        __syncthreads();
    }

    // ---- scatter kept entries into output ----
    int kc = kcount;
    for (int t = tid; t < kc; t += NT) {
        int i = kid[t];
        out[c * AN + i] = ksc[t];
        out[CA + c * AN + i] = (float)c;
        ((float4*)(out + 2 * CA))[c * AN + i] = kbox[t];
        out[6 * CA + c * AN + i] = 1.0f;
    }
}

// ---------------------------------------------------------------------------
extern "C" void kernel_launch(void* const* d_in, const int* in_sizes, int n_in,
                              void* d_out, int out_size) {
    const float* classification = (const float*)d_in[0];  // [1, A, C]
    const float* regression = (const float*)d_in[1];      // [1, A, 4]
    const float* anchors = (const float*)d_in[2];         // [A, 4]
    float* out = (float*)d_out;

    decode_kernel<<<(AN + 255) / 256, 256>>>(anchors, regression);
    gather_kernel<<<(CA + 255) / 256, 256>>>(classification);

    // zeros via memset nodes (scores region + boxes/keep tail), -1 labels via kernel
    cudaMemsetAsync(out, 0, (size_t)CA * sizeof(float), 0);
    cudaMemsetAsync(out + 2 * (size_t)CA, 0, (size_t)5 * CA * sizeof(float), 0);
    label_kernel<<<(CA / 4 + 255) / 256, 256>>>((float4*)(out + CA));

    nms_kernel<<<NC, NT>>>(classification, out);
}

// round 7
// speedup vs baseline: 3.6260x; 1.0003x over previous
#include <cuda_runtime.h>

#define AN 76725
#define NC 80
#define CA (AN * NC)
#define CAP 2048
#define MAXKEEP 200
#define IMGF 640.0f
#define T_HI 0.99f
#define T_LO 0.97f
#define NT 1024
#define NB 64
#define FULLW 0xFFFFFFFFu

// Scratch (device globals: no allocation allowed)
__device__ float g_boxes[AN * 4];  // decoded boxes
__device__ float g_area[AN];
__device__ unsigned long long g_cand[2][NC][CAP];  // per-tier per-class (score,idx) keys
__device__ int g_cnt[2][NC];
// compact per-class NMS results (decouples NMS from the big output buffer)
__device__ int g_kcnt[NC];
__device__ float4 g_kboxg[NC][MAXKEEP];
__device__ float g_kscg[NC][MAXKEEP];
__device__ int g_kidg[NC][MAXKEEP];

// ---------------------------------------------------------------------------
__global__ void decode_kernel(const float* __restrict__ anchors,
                              const float* __restrict__ reg) {
    int i = blockIdx.x * blockDim.x + threadIdx.x;
    if (i < 2 * NC) ((int*)g_cnt)[i] = 0;
    if (i >= AN) return;
    float a0 = anchors[i * 4 + 0], a1 = anchors[i * 4 + 1];
    float a2 = anchors[i * 4 + 2], a3 = anchors[i * 4 + 3];
    float r0 = reg[i * 4 + 0], r1 = reg[i * 4 + 1];
    float r2 = reg[i * 4 + 2], r3 = reg[i * 4 + 3];
    float aw = a2 - a0, ah = a3 - a1;
    float ax = a0 + 0.5f * aw, ay = a1 + 0.5f * ah;
    float cx = ax + r0 * 0.1f * aw;
    float cy = ay + r1 * 0.1f * ah;
    float w = aw * expf(r2 * 0.2f);
    float h = ah * expf(r3 * 0.2f);
    float x1 = fminf(fmaxf(cx - 0.5f * w, 0.0f), IMGF);
    float y1 = fminf(fmaxf(cy - 0.5f * h, 0.0f), IMGF);
    float x2 = fminf(fmaxf(cx + 0.5f * w, 0.0f), IMGF);
    float y2 = fminf(fmaxf(cy + 0.5f * h, 0.0f), IMGF);
    g_boxes[i * 4 + 0] = x1;
    g_boxes[i * 4 + 1] = y1;
    g_boxes[i * 4 + 2] = x2;
    g_boxes[i * 4 + 3] = y2;
    g_area[i] = (x2 - x1) * (y2 - y1);
}

// ---------------------------------------------------------------------------
__global__ void gather_kernel(const float* __restrict__ cls) {
    int idx = blockIdx.x * blockDim.x + threadIdx.x;
    if (idx >= CA) return;
    float s = cls[idx];
    if (s > T_LO) {
        int c = idx % NC;
        int a = idx / NC;
        int tier = (s > T_HI) ? 0 : 1;
        int p = atomicAdd(&g_cnt[tier][c], 1);
        if (p < CAP)
            g_cand[tier][c][p] = ((unsigned long long)__float_as_uint(s) << 32) |
                                 (unsigned long long)(0xFFFFFFFFu - (unsigned)a);
    }
}

// ---------------------------------------------------------------------------
// Fused default fill: zeros everywhere except labels region (-1.0f)
__global__ void fill_kernel(float4* __restrict__ out4, int n4) {
    const int ca4 = CA / 4;
    int stride = gridDim.x * blockDim.x;
    for (int i = blockIdx.x * blockDim.x + threadIdx.x; i < n4; i += stride) {
        float v = (i >= ca4 && i < 2 * ca4) ? -1.0f : 0.0f;
        out4[i] = make_float4(v, v, v, v);
    }
}

// ---------------------------------------------------------------------------
// Tiny scatter: overwrite kept entries in the filled output
__global__ void scatter_kernel(float* __restrict__ out) {
    int c = blockIdx.x;
    int kc = g_kcnt[c];
    for (int t = threadIdx.x; t < kc; t += blockDim.x) {
        int i = g_kidg[c][t];
        out[c * AN + i] = g_kscg[c][t];
        out[CA + c * AN + i] = (float)c;
        ((float4*)(out + 2 * CA))[c * AN + i] = g_kboxg[c][t];
        out[6 * CA + c * AN + i] = 1.0f;
    }
}

// ---------------------------------------------------------------------------
// Per-class NMS, 1024 threads/block, 64-candidate batches with uint64 masks.
// Writes compact results to device globals (not the big output buffer).
// ---------------------------------------------------------------------------
__global__ __launch_bounds__(NT) void nms_kernel(const float* __restrict__ cls) {
    const int c = blockIdx.x;
    const int tid = threadIdx.x;
    const int lane = tid & 31, wid = tid >> 5;

    __shared__ unsigned long long skey[CAP];        // 16KB (fallback: supp bitmap)
    __shared__ unsigned long long cmask64[NB];      // conflict rows (symmetric)
    __shared__ float4 bbox[NB];
    __shared__ float bar_[NB], bsc[NB];
    __shared__ int bidx[NB];
    __shared__ float4 kbox[MAXKEEP];
    __shared__ float kar[MAXKEEP], ksc[MAXKEEP];
    __shared__ int kid[MAXKEEP];
    __shared__ unsigned confParts[32];
    __shared__ unsigned long long alive64_s, km64_s;
    __shared__ unsigned long long red32[32];        // fallback warp-reduce
    __shared__ int kcount;

    unsigned* cmW = (unsigned*)cmask64;
    unsigned* kmW = (unsigned*)&km64_s;

    if (tid == 0) kcount = 0;
    __syncthreads();

    bool ok = true;
    for (int tier = 0; tier < 2; tier++) {
        if (kcount >= MAXKEEP) break;
        int n = g_cnt[tier][c];
        if (n > CAP) { ok = false; break; }
        if (n == 0) continue;

        // ---- load + pad + bitonic sort descending ----
        for (int i = tid; i < n; i += NT) skey[i] = g_cand[tier][c][i];
        int m = 1;
        while (m < n) m <<= 1;
        for (int i = n + tid; i < m; i += NT) skey[i] = 0ULL;
        __syncthreads();
        for (int k = 2; k <= m; k <<= 1) {
            for (int j = k >> 1; j > 0; j >>= 1) {
                for (int i = tid; i < m; i += NT) {
                    int ixj = i ^ j;
                    if (ixj > i) {
                        bool desc = ((i & k) == 0);
                        unsigned long long A = skey[i], B2 = skey[ixj];
                        if (desc ? (A < B2) : (A > B2)) { skey[i] = B2; skey[ixj] = A; }
                    }
                }
                __syncthreads();
            }
        }

        // ---- batched walk, NB=64 ----
        for (int base = 0; base < n; base += NB) {
            if (kcount >= MAXKEEP) break;
            int nb = min(NB, n - base);

            if (tid < nb) {
                unsigned long long key = skey[base + tid];
                float s = __uint_as_float((unsigned)(key >> 32));
                int idx = (int)(0xFFFFFFFFu - (unsigned)key);
                float4 bb;
                bb.x = g_boxes[idx * 4 + 0];
                bb.y = g_boxes[idx * 4 + 1];
                bb.z = g_boxes[idx * 4 + 2];
                bb.w = g_boxes[idx * 4 + 3];
                bbox[tid] = bb;
                bar_[tid] = g_area[idx];
                bsc[tid] = s;
                bidx[tid] = idx;
            }
            __syncthreads();

            int i = tid & 63;
            int g = tid >> 6;  // 0..15
            bool have = i < nb;
            float4 mb = make_float4(0, 0, 0, 0);
            float ma = 0;
            if (have) { mb = bbox[i]; ma = bar_[i]; }

            // phase 1a: conflict vs kept list, 16-way split per candidate
            int kc = kcount;
            bool cfk = false;
            if (have) {
                for (int j = g; j < kc; j += 16) {
                    float4 kb = kbox[j];
                    float ix1 = fmaxf(kb.x, mb.x), iy1 = fmaxf(kb.y, mb.y);
                    float ix2 = fminf(kb.z, mb.z), iy2 = fminf(kb.w, mb.w);
                    float inter = fmaxf(ix2 - ix1, 0.0f) * fmaxf(iy2 - iy1, 0.0f);
                    if (inter > 0.0f) {
                        float iou = inter / ((kar[j] + ma) - inter);
                        if (iou > 0.5f) { cfk = true; break; }
                    }
                }
            }
            unsigned cb = __ballot_sync(FULLW, cfk);
            if (lane == 0) confParts[wid] = cb;
            __syncthreads();
            if (tid == 0) {
                unsigned lo = 0, hi2 = 0;
                #pragma unroll
                for (int w = 0; w < 32; w += 2) { lo |= confParts[w]; hi2 |= confParts[w + 1]; }
                unsigned long long conf = ((unsigned long long)hi2 << 32) | lo;
                unsigned long long hv = (nb >= 64) ? ~0ULL : ((1ULL << nb) - 1ULL);
                alive64_s = hv & ~conf;
            }
            __syncthreads();
            unsigned long long alive64 = alive64_s;

            // phase 1b: conflict matrix, 16 columns per ballot round (<=4 rounds)
            for (int jb = 0; jb < nb; jb += 16) {
                int j = jb + g;
                bool cf = false;
                if (have && j < nb && i != j) {
                    float4 jb4 = bbox[j];
                    float ja = bar_[j];
                    float ix1 = fmaxf(jb4.x, mb.x), iy1 = fmaxf(jb4.y, mb.y);
                    float ix2 = fminf(jb4.z, mb.z), iy2 = fminf(jb4.w, mb.w);
                    float inter = fmaxf(ix2 - ix1, 0.0f) * fmaxf(iy2 - iy1, 0.0f);
                    if (inter > 0.0f) {
                        float iou = inter / ((ja + ma) - inter);
                        cf = iou > 0.5f;
                    }
                }
                unsigned bits = __ballot_sync(FULLW, cf);
                if (lane == 0 && j < nb) cmW[2 * j + (wid & 1)] = bits;
            }
            __syncthreads();

            // classify trivial/deferred (threads 0..63 = warps 0,1)
            {
                bool trivial = false, deferred = false;
                if (tid < 64) {
                    if ((alive64 >> tid) & 1ULL) {
                        unsigned long long below = (1ULL << tid) - 1ULL;
                        unsigned long long conf = cmask64[tid] & alive64 & below;
                        trivial = (conf == 0ULL);
                        deferred = !trivial;
                    }
                }
                unsigned tb = __ballot_sync(FULLW, trivial);
                unsigned db = __ballot_sync(FULLW, deferred);
                if (lane == 0 && wid < 2) kmW[wid] = tb;
                if (lane == 1 && wid < 2) red32[wid] = db;  // stash deferred halves
            }
            __syncthreads();

            // thread 0: resolve deferred serially with 64-bit masks, truncate
            if (tid == 0) {
                unsigned long long kw = km64_s;
                unsigned long long dbits = ((unsigned long long)(unsigned)red32[1] << 32) |
                                           (unsigned)red32[0];
                while (dbits) {
                    int q = __ffsll((long long)dbits) - 1;
                    dbits &= dbits - 1ULL;
                    unsigned long long below = (1ULL << q) - 1ULL;
                    if ((cmask64[q] & kw & below) == 0ULL) kw |= (1ULL << q);
                }
                int rem = MAXKEEP - kcount;
                int p = __popcll(kw);
                while (p > rem) {
                    kw &= ~(0x8000000000000000ULL >> __clzll((long long)kw));
                    p--;
                }
                km64_s = kw;
            }
            __syncthreads();

            unsigned long long kw = km64_s;
            int kc0 = kcount;
            if (tid < 64 && ((kw >> tid) & 1ULL)) {
                int pos = kc0 + __popcll(kw & ((1ULL << tid) - 1ULL));
                kbox[pos] = bbox[tid];
                kar[pos] = bar_[tid];
                ksc[pos] = bsc[tid];
                kid[pos] = bidx[tid];
            }
            __syncthreads();
            if (tid == 0) kcount = kc0 + __popcll(kw);
            __syncthreads();
        }
    }
    __syncthreads();

    // ---- Exact fallback (never triggered for this data) ----
    if (!ok || kcount < MAXKEEP) {
        unsigned* supp = (unsigned*)skey;  // 9.6KB of 16KB
        const int NW = (AN + 31) / 32;
        for (int w2 = tid; w2 < NW; w2 += NT) supp[w2] = 0u;
        if (tid == 0) kcount = 0;
        __syncthreads();
        for (int it = 0; it < MAXKEEP; it++) {
            unsigned long long best = 0ULL;
            for (int i = tid; i < AN; i += NT) {
                if (!((supp[i >> 5] >> (i & 31)) & 1u)) {
                    float s = cls[i * NC + c];
                    if (s > 0.1f) {
                        unsigned long long k =
                            ((unsigned long long)__float_as_uint(s) << 32) |
                            (unsigned long long)(0xFFFFFFFFu - (unsigned)i);
                        if (k > best) best = k;
                    }
                }
            }
            #pragma unroll
            for (int off = 16; off > 0; off >>= 1) {
                unsigned long long o = __shfl_down_sync(FULLW, best, off);
                if (o > best) best = o;
            }
            if (lane == 0) red32[wid] = best;
            __syncthreads();
            if (tid == 0) {
                unsigned long long b2 = red32[0];
                for (int w = 1; w < 32; w++)
                    if (red32[w] > b2) b2 = red32[w];
                red32[0] = b2;
            }
            __syncthreads();
            unsigned long long bk = red32[0];
            __syncthreads();
            if (bk == 0ULL) break;
            int bi = (int)(0xFFFFFFFFu - (unsigned)bk);
            float s = __uint_as_float((unsigned)(bk >> 32));
            float zx1 = g_boxes[bi * 4 + 0], zy1 = g_boxes[bi * 4 + 1];
            float zx2 = g_boxes[bi * 4 + 2], zy2 = g_boxes[bi * 4 + 3];
            float za = g_area[bi];
            if (tid == 0) {
                int kc2 = kcount;
                kbox[kc2] = make_float4(zx1, zy1, zx2, zy2);
                kar[kc2] = za; ksc[kc2] = s; kid[kc2] = bi;
                kcount = kc2 + 1;
            }
            for (int i = tid; i < AN; i += NT) {
                float ix1 = fmaxf(zx1, g_boxes[i * 4 + 0]);
                float iy1 = fmaxf(zy1, g_boxes[i * 4 + 1]);
                float ix2 = fminf(zx2, g_boxes[i * 4 + 2]);
                float iy2 = fminf(zy2, g_boxes[i * 4 + 3]);
                float inter = fmaxf(ix2 - ix1, 0.0f) * fmaxf(iy2 - iy1, 0.0f);
                float iou = inter / ((za + g_area[i]) - inter);
                if (iou > 0.5f || i == bi) atomicOr(&supp[i >> 5], 1u << (i & 31));
            }
            __syncthreads();
        }
        __syncthreads();
    }

    // ---- write compact results to device globals ----
    int kc = kcount;
    if (tid == 0) g_kcnt[c] = kc;
    for (int t = tid; t < kc; t += NT) {
        g_kboxg[c][t] = kbox[t];
        g_kscg[c][t] = ksc[t];
        g_kidg[c][t] = kid[t];
    }
}

// ---------------------------------------------------------------------------
extern "C" void kernel_launch(void* const* d_in, const int* in_sizes, int n_in,
                              void* d_out, int out_size) {
    const float* classification = (const float*)d_in[0];  // [1, A, C]
    const float* regression = (const float*)d_in[1];      // [1, A, 4]
    const float* anchors = (const float*)d_in[2];         // [A, 4]
    float* out = (float*)d_out;

    // One-time host-side resources (created on the first, non-captured call;
    // no device memory is allocated — streams/events are host objects).
    static cudaStream_t s_fill = nullptr;
    static cudaEvent_t ev_fork = nullptr, ev_join = nullptr;
    if (s_fill == nullptr) {
        cudaStreamCreateWithFlags(&s_fill, cudaStreamNonBlocking);
        cudaEventCreateWithFlags(&ev_fork, cudaEventDisableTiming);
        cudaEventCreateWithFlags(&ev_join, cudaEventDisableTiming);
    }

    // Fork: big output fill runs on s_fill, concurrent with the NMS pipeline.
    cudaEventRecord(ev_fork, 0);
    cudaStreamWaitEvent(s_fill, ev_fork, 0);
    int n4 = out_size / 4;
    fill_kernel<<<8192, 256, 0, s_fill>>>((float4*)out, n4);
    cudaEventRecord(ev_join, s_fill);

    // NMS pipeline on the capture stream.
    decode_kernel<<<(AN + 255) / 256, 256>>>(anchors, regression);
    gather_kernel<<<(CA + 255) / 256, 256>>>(classification);
    nms_kernel<<<NC, NT>>>(classification);

    // Join, then scatter kept entries into the filled output.
    cudaStreamWaitEvent(0, ev_join, 0);
    scatter_kernel<<<NC, 256>>>(out);
}